// round 3
// baseline (speedup 1.0000x reference)
#include <cuda_runtime.h>
#include <cstdint>
#include <math.h>

#define Bb   4
#define Tt   8192
#define Dd   1024
#define Ff   4096
#define CAP  4096
#define MTOT (Bb*CAP)   // 16384 selected tokens total

// ---------------- scratch (device globals: allocation-free rule) ------------
__device__ float g_scores[Bb*Tt];
__device__ int   g_sel[MTOT];                       // token idx within row, grouped per b
__device__ float g_h[(size_t)MTOT * (size_t)Ff];    // 256 MB hidden activations

// ---------------------------------------------------------------------------
// Kernel 1: router scores  s[b,t] = x[b,t,:] . w_router
// one warp per token, float4 loads, deterministic butterfly reduction
// ---------------------------------------------------------------------------
__global__ void scores_kernel(const float* __restrict__ x, const float* __restrict__ wr)
{
    int gw   = (blockIdx.x * blockDim.x + threadIdx.x) >> 5;   // token id, exact grid
    int lane = threadIdx.x & 31;
    const float* xr = x + (size_t)gw * Dd;
    float s = 0.f;
    #pragma unroll
    for (int i = 0; i < Dd; i += 128) {
        float4 a = *(const float4*)(xr + i + lane*4);
        float4 w = *(const float4*)(wr + i + lane*4);
        s += a.x*w.x; s += a.y*w.y; s += a.z*w.z; s += a.w*w.w;
    }
    #pragma unroll
    for (int o = 16; o; o >>= 1) s += __shfl_xor_sync(0xffffffffu, s, o);
    if (lane == 0) g_scores[gw] = s;
}

// ---------------------------------------------------------------------------
// Kernel 2: per-row top-CAP selection (radix select on sign-flipped float bits)
// One block per batch row, 1024 threads. Produces the selected SET (order
// irrelevant for correctness); ties at the threshold taken lowest-index-first
// to match jax.lax.top_k stability.
// ---------------------------------------------------------------------------
__global__ void select_kernel()
{
    __shared__ unsigned keys[Tt];       // 32 KB
    __shared__ int      hist[256];
    __shared__ int      scn[1024];
    __shared__ unsigned s_prefix;
    __shared__ int      s_k, s_cnt, s_pos;

    const int b = blockIdx.x;
    const int t = threadIdx.x;

    for (int i = t; i < Tt; i += 1024) {
        unsigned u = __float_as_uint(g_scores[b*Tt + i]);
        u = (u & 0x80000000u) ? ~u : (u | 0x80000000u);   // monotonic: bigger key = bigger float
        keys[i] = u;
    }
    if (t == 0) { s_prefix = 0u; s_k = CAP; }
    __syncthreads();

    // 4-pass radix select: find the CAP-th largest key exactly
    for (int shift = 24; shift >= 0; shift -= 8) {
        if (t < 256) hist[t] = 0;
        __syncthreads();
        unsigned hi  = (shift == 24) ? 0u : (0xFFFFFFFFu << (shift + 8));
        unsigned pfx = s_prefix;
        for (int i = t; i < Tt; i += 1024) {
            unsigned k = keys[i];
            if ((k & hi) == pfx) atomicAdd(&hist[(k >> shift) & 255], 1);
        }
        __syncthreads();
        if (t == 0) {
            int k = s_k, bin;
            for (bin = 255; bin > 0; bin--) {
                int c = hist[bin];
                if (c >= k) break;
                k -= c;
            }
            s_prefix |= ((unsigned)bin) << shift;
            s_k = k;
        }
        __syncthreads();
    }
    const unsigned thresh = s_prefix;   // exact CAP-th largest key

    if (t == 0) { s_cnt = 0; s_pos = 0; }
    __syncthreads();
    int loc = 0;
    for (int i = t; i < Tt; i += 1024) if (keys[i] > thresh) loc++;
    atomicAdd(&s_cnt, loc);
    __syncthreads();
    const int greater = s_cnt;
    const int need    = CAP - greater;   // >= 1 ties to take (lowest index first)

    // strictly-greater keys: any order
    for (int i = t; i < Tt; i += 1024)
        if (keys[i] > thresh) { int p = atomicAdd(&s_pos, 1); g_sel[b*CAP + p] = i; }

    // ties: index-ordered via blocked scan (thread t owns indices [8t, 8t+8))
    int cnt = 0;
    #pragma unroll
    for (int j = 0; j < 8; j++) if (keys[t*8 + j] == thresh) cnt++;
    scn[t] = cnt;
    __syncthreads();
    for (int off = 1; off < 1024; off <<= 1) {
        int v = (t >= off) ? scn[t - off] : 0;
        __syncthreads();
        scn[t] += v;
        __syncthreads();
    }
    int r = scn[t] - cnt;   // exclusive prefix of ties before my chunk
    #pragma unroll
    for (int j = 0; j < 8; j++) {
        int i = t*8 + j;
        if (keys[i] == thresh) {
            if (r < need) g_sel[b*CAP + greater + r] = i;
            r++;
        }
    }
}

// ---------------------------------------------------------------------------
// tf32 GEMM (mma.sync.m16n8k8), 128x128x32 tiles, 8 warps, double-buffered.
// PH1: C = gelu_tanh(gather(x) @ w1 + b1) -> g_h      (K=1024, N=4096)
// PH2: scatter(out) = g_h @ w2 + b2                   (K=4096, N=1024)
// ---------------------------------------------------------------------------
#define BM  128
#define BN  128
#define BK  32
#define AST 36      // A smem stride: bank = 4*(lane/4)+lane%4 -> conflict-free
#define BST 136     // B smem stride: bank = 8*(lane%4)+lane/4 -> conflict-free
#define SMEM_BYTES ((2*BM*AST + 2*BK*BST) * 4)   // 71680 B

__device__ __forceinline__ unsigned cvt_tf32(float f) {
    unsigned u; asm("cvt.rna.tf32.f32 %0, %1;" : "=r"(u) : "f"(f)); return u;
}
__device__ __forceinline__ void mma8(float* d, const unsigned* a, const unsigned* b) {
    asm volatile(
        "mma.sync.aligned.m16n8k8.row.col.f32.tf32.tf32.f32 "
        "{%0,%1,%2,%3},{%4,%5,%6,%7},{%8,%9},{%0,%1,%2,%3};\n"
        : "+f"(d[0]), "+f"(d[1]), "+f"(d[2]), "+f"(d[3])
        : "r"(a[0]), "r"(a[1]), "r"(a[2]), "r"(a[3]), "r"(b[0]), "r"(b[1]));
}
__device__ __forceinline__ float gelu_t(float x) {   // jax.nn.gelu approximate=True
    float u = 0.7978845608028654f * (x + 0.044715f * x * x * x);
    return 0.5f * x * (1.0f + tanhf(u));
}

template<int KD, int ND, bool PH1>
__global__ void __launch_bounds__(256)
gemm_tf32(const float* __restrict__ Aglob,   // PH1: x base (gathered); PH2: unused
          const float* __restrict__ Bw,      // [KD][ND] row-major
          const float* __restrict__ bias,    // [ND]
          float* __restrict__ Cglob)         // PH2: out base (scattered); PH1: unused
{
    extern __shared__ float sm[];
    float* As = sm;
    float* Bs = sm + 2*BM*AST;

    const int tid  = threadIdx.x;
    const int warp = tid >> 5, lane = tid & 31;
    const int m0   = blockIdx.y * BM;
    const int n0   = blockIdx.x * BN;

    const float* Asrc = PH1 ? Aglob : (const float*)g_h;
    float*       Cdst = PH1 ? (float*)g_h : Cglob;

    // per-thread A row pointers (4 float4 loads per tile; id = tid + 256*j)
    const float* arow[4];
    #pragma unroll
    for (int j = 0; j < 4; j++) {
        int id = tid + 256*j;
        int r  = m0 + (id >> 3);
        if (PH1) {
            int bb = r >> 12;             // CAP = 4096 rows per batch
            int tok = g_sel[r];
            arow[j] = Asrc + ((size_t)(bb*Tt + tok)) * (size_t)KD;
        } else {
            arow[j] = Asrc + (size_t)r * (size_t)KD;
        }
    }
    const float* brow[4];
    #pragma unroll
    for (int j = 0; j < 4; j++) {
        int id = tid + 256*j;
        brow[j] = Bw + (size_t)(id >> 5) * ND + n0 + ((id & 31) << 2);
    }

    float acc[4][4][4];
    #pragma unroll
    for (int i = 0; i < 4; i++)
        #pragma unroll
        for (int jn = 0; jn < 4; jn++)
            #pragma unroll
            for (int q = 0; q < 4; q++) acc[i][jn][q] = 0.f;

    const int nk = KD / BK;

    // prologue: stage tile 0 into buffer 0 (fp32 -> tf32 RNA at smem-store time)
    {
        float* Ad = As; float* Bd = Bs;
        #pragma unroll
        for (int j = 0; j < 4; j++) {
            int id = tid + 256*j;
            int r = id >> 3, kc = (id & 7) << 2;
            float4 v = *(const float4*)(arow[j] + kc);
            uint4 u = make_uint4(cvt_tf32(v.x), cvt_tf32(v.y), cvt_tf32(v.z), cvt_tf32(v.w));
            *(uint4*)(Ad + r*AST + kc) = u;
        }
        #pragma unroll
        for (int j = 0; j < 4; j++) {
            int id = tid + 256*j;
            int r = id >> 5, c = (id & 31) << 2;
            float4 v = *(const float4*)(brow[j]);
            uint4 u = make_uint4(cvt_tf32(v.x), cvt_tf32(v.y), cvt_tf32(v.z), cvt_tf32(v.w));
            *(uint4*)(Bd + r*BST + c) = u;
        }
    }
    __syncthreads();

    for (int kt = 0; kt < nk; kt++) {
        // stage next tile into the other buffer (overlaps with compute below)
        if (kt + 1 < nk) {
            int buf = (kt + 1) & 1;
            float* Ad = As + buf*BM*AST;
            float* Bd = Bs + buf*BK*BST;
            int kofs = (kt + 1) * BK;
            #pragma unroll
            for (int j = 0; j < 4; j++) {
                int id = tid + 256*j;
                int r = id >> 3, kc = (id & 7) << 2;
                float4 v = *(const float4*)(arow[j] + kofs + kc);
                uint4 u = make_uint4(cvt_tf32(v.x), cvt_tf32(v.y), cvt_tf32(v.z), cvt_tf32(v.w));
                *(uint4*)(Ad + r*AST + kc) = u;
            }
            #pragma unroll
            for (int j = 0; j < 4; j++) {
                int id = tid + 256*j;
                int r = id >> 5, c = (id & 31) << 2;
                float4 v = *(const float4*)(brow[j] + (size_t)kofs * ND);
                uint4 u = make_uint4(cvt_tf32(v.x), cvt_tf32(v.y), cvt_tf32(v.z), cvt_tf32(v.w));
                *(uint4*)(Bd + r*BST + c) = u;
            }
        }

        const unsigned* Ad = (const unsigned*)(As + (kt & 1)*BM*AST);
        const unsigned* Bd = (const unsigned*)(Bs + (kt & 1)*BK*BST);
        const int wm = (warp >> 2) * 64, wn = (warp & 3) * 32;

        #pragma unroll
        for (int k8 = 0; k8 < BK; k8 += 8) {
            unsigned af[4][4], bf[4][2];
            #pragma unroll
            for (int mt = 0; mt < 4; mt++) {
                int row = wm + mt*16 + (lane >> 2);
                int col = k8 + (lane & 3);
                af[mt][0] = Ad[row*AST + col];
                af[mt][1] = Ad[(row+8)*AST + col];
                af[mt][2] = Ad[row*AST + col + 4];
                af[mt][3] = Ad[(row+8)*AST + col + 4];
            }
            #pragma unroll
            for (int nt = 0; nt < 4; nt++) {
                int kr  = k8 + (lane & 3);
                int col = wn + nt*8 + (lane >> 2);
                bf[nt][0] = Bd[kr*BST + col];
                bf[nt][1] = Bd[(kr+4)*BST + col];
            }
            #pragma unroll
            for (int mt = 0; mt < 4; mt++)
                #pragma unroll
                for (int nt = 0; nt < 4; nt++)
                    mma8(acc[mt][nt], af[mt], bf[nt]);
        }
        __syncthreads();
    }

    // epilogue: bias (+gelu for PH1), write rows (PH1: linear g_h; PH2: scatter)
    const int wm = (warp >> 2) * 64, wn = (warp & 3) * 32;
    #pragma unroll
    for (int mt = 0; mt < 4; mt++) {
        #pragma unroll
        for (int half = 0; half < 2; half++) {
            int row = m0 + wm + mt*16 + (lane >> 2) + half*8;
            size_t obase;
            if (PH1) {
                obase = (size_t)row * ND;
            } else {
                int bb = row >> 12;
                int tok = g_sel[row];
                obase = ((size_t)(bb*Tt + tok)) * (size_t)ND;
            }
            #pragma unroll
            for (int nt = 0; nt < 4; nt++) {
                int col = n0 + wn + nt*8 + (lane & 3)*2;
                float v0 = acc[mt][nt][half*2 + 0] + bias[col];
                float v1 = acc[mt][nt][half*2 + 1] + bias[col + 1];
                if (PH1) { v0 = gelu_t(v0); v1 = gelu_t(v1); }
                float2 v = make_float2(v0, v1);
                *(float2*)(Cdst + obase + col) = v;
            }
        }
    }
}

// ---------------------------------------------------------------------------
extern "C" void kernel_launch(void* const* d_in, const int* in_sizes, int n_in,
                              void* d_out, int out_size)
{
    const float* x  = (const float*)d_in[0];
    const float* wr = (const float*)d_in[1];
    const float* w1 = (const float*)d_in[2];
    const float* b1 = (const float*)d_in[3];
    const float* w2 = (const float*)d_in[4];
    const float* b2 = (const float*)d_in[5];
    float* out = (float*)d_out;

    // 1) router scores
    scores_kernel<<<(Bb*Tt)/8, 256>>>(x, wr);
    // 2) per-row top-k selection
    select_kernel<<<Bb, 1024>>>();
    // 3) passthrough copy (selected rows overwritten by GEMM2 scatter)
    cudaMemcpyAsync(out, x, (size_t)Bb*Tt*Dd*sizeof(float),
                    cudaMemcpyDeviceToDevice, 0);
    // 4) FFN GEMM1 (gather + gelu) and GEMM2 (scatter)
    cudaFuncSetAttribute(gemm_tf32<Dd, Ff, true>,
                         cudaFuncAttributeMaxDynamicSharedMemorySize, SMEM_BYTES);
    cudaFuncSetAttribute(gemm_tf32<Ff, Dd, false>,
                         cudaFuncAttributeMaxDynamicSharedMemorySize, SMEM_BYTES);
    dim3 g1(Ff/BN, MTOT/BM);   // 32 x 128
    dim3 g2(Dd/BN, MTOT/BM);   //  8 x 128
    gemm_tf32<Dd, Ff, true ><<<g1, 256, SMEM_BYTES>>>(x, w1, b1, nullptr);
    gemm_tf32<Ff, Dd, false><<<g2, 256, SMEM_BYTES>>>(nullptr, w2, b2, out);
}

// round 7
// speedup vs baseline: 1.5875x; 1.5875x over previous
#include <cuda_runtime.h>
#include <cstdint>
#include <math.h>

#define Bb   4
#define Tt   8192
#define Dd   1024
#define Ff   4096
#define CAP  4096
#define MTOT (Bb*CAP)   // 16384 selected tokens

// ---------------- scratch (device globals: allocation-free rule) ------------
__device__ float g_scores[Bb*Tt];
__device__ int   g_sel[MTOT];
__device__ __align__(16) float g_xg[(size_t)MTOT * (size_t)Dd];   // gathered+rounded x (64MB)
__device__ __align__(16) float g_h [(size_t)MTOT * (size_t)Ff];   // hidden, tf32-rounded (256MB)
__device__ __align__(16) float g_w1r[(size_t)Dd * (size_t)Ff];    // w1 rounded (16MB)
__device__ __align__(16) float g_w2r[(size_t)Ff * (size_t)Dd];    // w2 rounded (16MB)

// ---------------------------------------------------------------------------
__device__ __forceinline__ unsigned cvt_tf32(float f) {
    unsigned u; asm("cvt.rna.tf32.f32 %0, %1;" : "=r"(u) : "f"(f)); return u;
}
__device__ __forceinline__ float rnd_tf32(float f) { return __uint_as_float(cvt_tf32(f)); }
__device__ __forceinline__ uint32_t smem_u32(const void* p) {
    uint32_t a;
    asm("{ .reg .u64 t; cvta.to.shared.u64 t, %1; cvt.u32.u64 %0, t; }" : "=r"(a) : "l"(p));
    return a;
}
__device__ __forceinline__ void cp16(uint32_t dst, const float* src) {
    asm volatile("cp.async.cg.shared.global [%0], [%1], 16;" :: "r"(dst), "l"(src) : "memory");
}
#define CP_COMMIT() asm volatile("cp.async.commit_group;" ::: "memory")
#define CP_WAIT1()  asm volatile("cp.async.wait_group 1;" ::: "memory")

__device__ __forceinline__ void mma8(float* d, const unsigned* a, const unsigned* b) {
    asm volatile(
        "mma.sync.aligned.m16n8k8.row.col.f32.tf32.tf32.f32 "
        "{%0,%1,%2,%3},{%4,%5,%6,%7},{%8,%9},{%0,%1,%2,%3};\n"
        : "+f"(d[0]), "+f"(d[1]), "+f"(d[2]), "+f"(d[3])
        : "r"(a[0]), "r"(a[1]), "r"(a[2]), "r"(a[3]), "r"(b[0]), "r"(b[1]));
}
__device__ __forceinline__ float gelu_t(float x) {   // jax gelu approximate=True
    float u = 0.7978845608028654f * (x + 0.044715f * x * x * x);
    return 0.5f * x * (1.0f + tanhf(u));
}

// ---------------------------------------------------------------------------
// Kernel 1: router scores (one warp per token)
// ---------------------------------------------------------------------------
__global__ void scores_kernel(const float* __restrict__ x, const float* __restrict__ wr)
{
    int gw   = (blockIdx.x * blockDim.x + threadIdx.x) >> 5;
    int lane = threadIdx.x & 31;
    const float* xr = x + (size_t)gw * Dd;
    float s = 0.f;
    #pragma unroll
    for (int i = 0; i < Dd; i += 128) {
        float4 a = *(const float4*)(xr + i + lane*4);
        float4 w = *(const float4*)(wr + i + lane*4);
        s += a.x*w.x; s += a.y*w.y; s += a.z*w.z; s += a.w*w.w;
    }
    #pragma unroll
    for (int o = 16; o; o >>= 1) s += __shfl_xor_sync(0xffffffffu, s, o);
    if (lane == 0) g_scores[gw] = s;
}

// ---------------------------------------------------------------------------
// Kernel 2: per-row top-CAP radix select (ties lowest-index-first)
// ---------------------------------------------------------------------------
__global__ void select_kernel()
{
    __shared__ unsigned keys[Tt];
    __shared__ int      hist[256];
    __shared__ int      scn[1024];
    __shared__ unsigned s_prefix;
    __shared__ int      s_k, s_cnt, s_pos;

    const int b = blockIdx.x;
    const int t = threadIdx.x;

    for (int i = t; i < Tt; i += 1024) {
        unsigned u = __float_as_uint(g_scores[b*Tt + i]);
        u = (u & 0x80000000u) ? ~u : (u | 0x80000000u);
        keys[i] = u;
    }
    if (t == 0) { s_prefix = 0u; s_k = CAP; }
    __syncthreads();

    for (int shift = 24; shift >= 0; shift -= 8) {
        if (t < 256) hist[t] = 0;
        __syncthreads();
        unsigned hi  = (shift == 24) ? 0u : (0xFFFFFFFFu << (shift + 8));
        unsigned pfx = s_prefix;
        for (int i = t; i < Tt; i += 1024) {
            unsigned k = keys[i];
            if ((k & hi) == pfx) atomicAdd(&hist[(k >> shift) & 255], 1);
        }
        __syncthreads();
        if (t == 0) {
            int k = s_k, bin;
            for (bin = 255; bin > 0; bin--) {
                int c = hist[bin];
                if (c >= k) break;
                k -= c;
            }
            s_prefix |= ((unsigned)bin) << shift;
            s_k = k;
        }
        __syncthreads();
    }
    const unsigned thresh = s_prefix;

    if (t == 0) { s_cnt = 0; s_pos = 0; }
    __syncthreads();
    int loc = 0;
    for (int i = t; i < Tt; i += 1024) if (keys[i] > thresh) loc++;
    atomicAdd(&s_cnt, loc);
    __syncthreads();
    const int greater = s_cnt;
    const int need    = CAP - greater;

    for (int i = t; i < Tt; i += 1024)
        if (keys[i] > thresh) { int p = atomicAdd(&s_pos, 1); g_sel[b*CAP + p] = i; }

    int cnt = 0;
    #pragma unroll
    for (int j = 0; j < 8; j++) if (keys[t*8 + j] == thresh) cnt++;
    scn[t] = cnt;
    __syncthreads();
    for (int off = 1; off < 1024; off <<= 1) {
        int v = (t >= off) ? scn[t - off] : 0;
        __syncthreads();
        scn[t] += v;
        __syncthreads();
    }
    int r = scn[t] - cnt;
    #pragma unroll
    for (int j = 0; j < 8; j++) {
        int i = t*8 + j;
        if (keys[i] == thresh) {
            if (r < need) g_sel[b*CAP + greater + r] = i;
            r++;
        }
    }
}

// ---------------------------------------------------------------------------
// Kernel 3a: elementwise tf32 rounding (weights)
// ---------------------------------------------------------------------------
__global__ void round_kernel(const float* __restrict__ in, float* __restrict__ out, int n4)
{
    int i = blockIdx.x * blockDim.x + threadIdx.x;
    if (i < n4) {
        float4 v = ((const float4*)in)[i];
        v.x = rnd_tf32(v.x); v.y = rnd_tf32(v.y);
        v.z = rnd_tf32(v.z); v.w = rnd_tf32(v.w);
        ((float4*)out)[i] = v;
    }
}

// ---------------------------------------------------------------------------
// Kernel 3b: gather selected token rows + tf32 round -> packed g_xg
// one block (256 thr) per selected row
// ---------------------------------------------------------------------------
__global__ void gather_round_kernel(const float* __restrict__ x)
{
    int row = blockIdx.x;
    int bb  = row >> 12;
    int tok = g_sel[row];
    const float4* src = (const float4*)(x + (size_t)(bb*Tt + tok) * Dd);
    float4*       dst = (float4*)(g_xg + (size_t)row * Dd);
    float4 v = src[threadIdx.x];
    v.x = rnd_tf32(v.x); v.y = rnd_tf32(v.y);
    v.z = rnd_tf32(v.z); v.w = rnd_tf32(v.w);
    dst[threadIdx.x] = v;
}

// ---------------------------------------------------------------------------
// tf32 mma.sync GEMM, 128x128x32 tiles, 8 warps, cp.async triple-buffered.
// Operands pre-rounded to tf32 -> hot loop has ZERO cvt / register staging.
// PH1: g_h = tf32(gelu(g_xg @ w1r + b1))     (KD=1024, ND=4096)
// PH2: scatter(out) = g_h @ w2r + b2         (KD=4096, ND=1024)
// ---------------------------------------------------------------------------
#define BM  128
#define BN  128
#define BK  32
#define AST 36      // A smem stride (floats): conflict-free fragment LDS
#define BST 136     // B smem stride (floats): conflict-free fragment LDS
#define STG_FLOATS (BM*AST + BK*BST)          // 8960 floats / stage
#define SMEM_BYTES (3 * STG_FLOATS * 4)       // 107520 B -> 2 CTAs/SM

template<int KD, int ND, bool PH1>
__global__ void __launch_bounds__(256, 2)
gemm_tf32(const float* __restrict__ A,      // pre-rounded, row-major [rows][KD]
          const float* __restrict__ Bw,     // pre-rounded, row-major [KD][ND]
          const float* __restrict__ bias,
          float* __restrict__ C)
{
    extern __shared__ float sm[];
    const uint32_t smb = smem_u32(sm);
    const int tid  = threadIdx.x;
    const int warp = tid >> 5, lane = tid & 31;
    const int m0   = blockIdx.y * BM;
    const int n0   = blockIdx.x * BN;

    // staging maps: A = 1024 float4s, B = 1024 float4s, 4 each per thread
    const float* asrc[4]; uint32_t adst[4];
    #pragma unroll
    for (int j = 0; j < 4; j++) {
        int id = tid + 256*j;
        int r = id >> 3, c = (id & 7) << 2;
        asrc[j] = A + (size_t)(m0 + r) * KD + c;
        adst[j] = (uint32_t)(r*AST + c) * 4;
    }
    const float* bsrc[4]; uint32_t bdst[4];
    #pragma unroll
    for (int j = 0; j < 4; j++) {
        int id = tid + 256*j;
        int kr = id >> 5, c = (id & 31) << 2;
        bsrc[j] = Bw + (size_t)kr * ND + n0 + c;
        bdst[j] = (uint32_t)(BM*AST + kr*BST + c) * 4;
    }

    float acc[4][4][4];
    #pragma unroll
    for (int i = 0; i < 4; i++)
        #pragma unroll
        for (int jn = 0; jn < 4; jn++)
            #pragma unroll
            for (int q = 0; q < 4; q++) acc[i][jn][q] = 0.f;

    const int nk = KD / BK;

    // prologue: issue tiles 0, 1
    #pragma unroll
    for (int p = 0; p < 2; p++) {
        uint32_t sb = smb + (uint32_t)p * STG_FLOATS * 4;
        #pragma unroll
        for (int j = 0; j < 4; j++) cp16(sb + adst[j], asrc[j] + p*BK);
        #pragma unroll
        for (int j = 0; j < 4; j++) cp16(sb + bdst[j], bsrc[j] + (size_t)(p*BK) * ND);
        CP_COMMIT();
    }

    const int wm = (warp >> 2) * 64, wn = (warp & 3) * 32;

    for (int kt = 0; kt < nk; kt++) {
        CP_WAIT1();
        __syncthreads();

        const unsigned* Ad = (const unsigned*)(sm + (kt % 3) * STG_FLOATS);
        const unsigned* Bd = Ad + BM*AST;

        #pragma unroll
        for (int k8 = 0; k8 < BK; k8 += 8) {
            unsigned af[4][4], bf[4][2];
            #pragma unroll
            for (int mt = 0; mt < 4; mt++) {
                int row = wm + mt*16 + (lane >> 2);
                int col = k8 + (lane & 3);
                af[mt][0] = Ad[row*AST + col];
                af[mt][1] = Ad[(row+8)*AST + col];
                af[mt][2] = Ad[row*AST + col + 4];
                af[mt][3] = Ad[(row+8)*AST + col + 4];
            }
            #pragma unroll
            for (int nt = 0; nt < 4; nt++) {
                int kr  = k8 + (lane & 3);
                int col = wn + nt*8 + (lane >> 2);
                bf[nt][0] = Bd[kr*BST + col];
                bf[nt][1] = Bd[(kr+4)*BST + col];
            }
            #pragma unroll
            for (int mt = 0; mt < 4; mt++)
                #pragma unroll
                for (int nt = 0; nt < 4; nt++)
                    mma8(acc[mt][nt], af[mt], bf[nt]);
        }

        // issue tile kt+2 into the buffer consumed at iter kt-1 (safe: barrier above)
        if (kt + 2 < nk) {
            uint32_t sb = smb + (uint32_t)((kt+2) % 3) * STG_FLOATS * 4;
            int kofs = (kt + 2) * BK;
            #pragma unroll
            for (int j = 0; j < 4; j++) cp16(sb + adst[j], asrc[j] + kofs);
            #pragma unroll
            for (int j = 0; j < 4; j++) cp16(sb + bdst[j], bsrc[j] + (size_t)kofs * ND);
        }
        CP_COMMIT();   // always commit (keeps wait_group bookkeeping uniform)
        __syncthreads();
    }

    // epilogue: bias (+gelu+round for PH1); PH1 linear store, PH2 scatter
    #pragma unroll
    for (int mt = 0; mt < 4; mt++) {
        #pragma unroll
        for (int half = 0; half < 2; half++) {
            int row = m0 + wm + mt*16 + (lane >> 2) + half*8;
            size_t ob;
            if (PH1) ob = (size_t)row * ND;
            else { int bb = row >> 12; ob = ((size_t)(bb*Tt + g_sel[row])) * (size_t)ND; }
            #pragma unroll
            for (int nt = 0; nt < 4; nt++) {
                int col = n0 + wn + nt*8 + (lane & 3)*2;
                float v0 = acc[mt][nt][half*2 + 0] + bias[col];
                float v1 = acc[mt][nt][half*2 + 1] + bias[col + 1];
                if (PH1) { v0 = rnd_tf32(gelu_t(v0)); v1 = rnd_tf32(gelu_t(v1)); }
                *(float2*)(C + ob + col) = make_float2(v0, v1);
            }
        }
    }
}

// ---------------------------------------------------------------------------
extern "C" void kernel_launch(void* const* d_in, const int* in_sizes, int n_in,
                              void* d_out, int out_size)
{
    const float* x  = (const float*)d_in[0];
    const float* wr = (const float*)d_in[1];
    const float* w1 = (const float*)d_in[2];
    const float* b1 = (const float*)d_in[3];
    const float* w2 = (const float*)d_in[4];
    const float* b2 = (const float*)d_in[5];
    float* out = (float*)d_out;

    // 1) router + top-k
    scores_kernel<<<(Bb*Tt)/8, 256>>>(x, wr);
    select_kernel<<<Bb, 1024>>>();

    // 2) passthrough copy (selected rows overwritten by GEMM2 scatter)
    cudaMemcpyAsync(out, x, (size_t)Bb*Tt*Dd*sizeof(float),
                    cudaMemcpyDeviceToDevice, 0);

    // 3) operand pre-rounding (weights) + packed gather of selected tokens
    {
        float* w1r; cudaGetSymbolAddress((void**)&w1r, g_w1r);
        float* w2r; cudaGetSymbolAddress((void**)&w2r, g_w2r);
        int n4 = Dd*Ff/4;
        round_kernel<<<n4/256, 256>>>(w1, w1r, n4);
        round_kernel<<<n4/256, 256>>>(w2, w2r, n4);
        gather_round_kernel<<<MTOT, 256>>>(x);
    }

    // 4) FFN GEMMs (cp.async triple-buffered tf32 mma.sync)
    cudaFuncSetAttribute(gemm_tf32<Dd, Ff, true>,
                         cudaFuncAttributeMaxDynamicSharedMemorySize, SMEM_BYTES);
    cudaFuncSetAttribute(gemm_tf32<Ff, Dd, false>,
                         cudaFuncAttributeMaxDynamicSharedMemorySize, SMEM_BYTES);
    {
        float* xg;  cudaGetSymbolAddress((void**)&xg,  g_xg);
        float* h;   cudaGetSymbolAddress((void**)&h,   g_h);
        float* w1r; cudaGetSymbolAddress((void**)&w1r, g_w1r);
        float* w2r; cudaGetSymbolAddress((void**)&w2r, g_w2r);
        dim3 g1(Ff/BN, MTOT/BM);   // 32 x 128
        dim3 g2(Dd/BN, MTOT/BM);   //  8 x 128
        gemm_tf32<Dd, Ff, true ><<<g1, 256, SMEM_BYTES>>>(xg, w1r, b1, h);
        gemm_tf32<Ff, Dd, false><<<g2, 256, SMEM_BYTES>>>(h,  w2r, b2, out);
    }
}